// round 16
// baseline (speedup 1.0000x reference)
#include <cuda_runtime.h>
#include <cuda_fp16.h>
#include <mma.h>
#include <cstdint>

using namespace nvcuda;

#define N_NODES_MAX 100000
#define NFEAT 128

// Scratch (allocation-free rule: __device__ globals, referenced only in kernels)
__device__ __half g_XFh[(size_t)N_NODES_MAX * NFEAT];   // XF in fp16
__device__ int    g_rowptr[N_NODES_MAX + 1];            // CSR row pointer

// ---------------------------------------------------------------------------
// Kernel A: rowptr from sorted edge_dst — 4 edges/thread, one int4 load.
// Zero SMEM -> full occupancy, ~5us.
// ---------------------------------------------------------------------------
__global__ void rowptr_kernel(const int* __restrict__ edst, int E, int N) {
    const int t  = blockIdx.x * blockDim.x + threadIdx.x;
    const int e0 = t * 4;
    if (e0 >= E) return;

    int d[4];
    int nvalid;
    if (e0 + 4 <= E) {
        const int4 d4 = __ldg((const int4*)(edst + e0));
        d[0] = d4.x; d[1] = d4.y; d[2] = d4.z; d[3] = d4.w;
        nvalid = 4;
    } else {
        nvalid = E - e0;
        for (int i = 0; i < nvalid; i++) d[i] = __ldg(edst + e0 + i);
    }

    int prev = (e0 == 0) ? -1 : __ldg(edst + e0 - 1);
#pragma unroll
    for (int i = 0; i < 4; i++) {
        if (i < nvalid) {
            for (int dd = prev + 1; dd <= d[i]; dd++) g_rowptr[dd] = e0 + i;
            prev = d[i];
        }
    }
    if (e0 + 4 >= E) {
        for (int dd = prev + 1; dd <= N; dd++) g_rowptr[dd] = E;
    }
}

// ---------------------------------------------------------------------------
// Kernel B: tensor-core GEMM  XF[M,128] = x[M,128] @ filters[128,128]
// fp16 HMMA, fp32 accumulate, fp16 output. Inline filter fp32->fp16 convert.
// SMEM: Bs 34.8KB + As 17.4KB = 52.2KB (stage UNIONED into As after MMA)
// -> 4 blocks/SM for better load-phase overlap.
// ---------------------------------------------------------------------------
#define GB_BM 64
#define LDM 136   // 128 + 8 halves pad

__global__ __launch_bounds__(256)
void gemm_wmma_kernel(const float* __restrict__ A,
                      const float* __restrict__ F,
                      int M) {
    __shared__ __half Bs[NFEAT][LDM];          // filters fp16, 34.8KB
    __shared__ __half As[GB_BM][LDM];          // x tile fp16, 17.4KB (reused as stage)

    const int tid  = threadIdx.x;
    const int warp = tid >> 5;
    const int lane = tid & 31;
    const int block_row = blockIdx.x * GB_BM;

    // Inline filter convert: 4096 float4 groups, 16 per thread (coalesced)
#pragma unroll
    for (int i = 0; i < 16; i++) {
        const int g   = tid + i * 256;
        const int row = g >> 5;
        const int col = (g & 31) << 2;
        const float4 v = *(const float4*)(F + (size_t)row * NFEAT + col);
        *(__half2*)&Bs[row][col + 0] = __floats2half2_rn(v.x, v.y);
        *(__half2*)&Bs[row][col + 2] = __floats2half2_rn(v.z, v.w);
    }

    // Load + convert x tile: 64x128 fp32 -> fp16 SMEM (8 float4 per thread)
#pragma unroll
    for (int i = 0; i < 8; i++) {
        const int idx = tid + i * 256;
        const int row = idx >> 5;
        const int col = (idx & 31) << 2;
        const int gr  = block_row + row;
        float4 v;
        if (gr < M)
            v = *(const float4*)(A + (size_t)gr * NFEAT + col);
        else
            v = make_float4(0.f, 0.f, 0.f, 0.f);
        *(__half2*)&As[row][col + 0] = __floats2half2_rn(v.x, v.y);
        *(__half2*)&As[row][col + 2] = __floats2half2_rn(v.z, v.w);
    }
    __syncthreads();

    // MMA: warp owns 16 rows x 64 cols
    const int srow = (warp >> 1) * 16;
    const int scol = (warp & 1) * 64;

    wmma::fragment<wmma::accumulator, 16, 16, 16, float> acc[4];
#pragma unroll
    for (int ct = 0; ct < 4; ct++) wmma::fill_fragment(acc[ct], 0.0f);

#pragma unroll
    for (int kt = 0; kt < 8; kt++) {
        wmma::fragment<wmma::matrix_a, 16, 16, 16, __half, wmma::row_major> a_frag;
        wmma::load_matrix_sync(a_frag, &As[srow][kt * 16], LDM);
#pragma unroll
        for (int ct = 0; ct < 4; ct++) {
            wmma::fragment<wmma::matrix_b, 16, 16, 16, __half, wmma::row_major> b_frag;
            wmma::load_matrix_sync(b_frag, &Bs[kt * 16][scol + ct * 16], LDM);
            wmma::mma_sync(acc[ct], a_frag, b_frag, acc[ct]);
        }
    }

    // As is dead now — reuse its storage as the per-warp f32 staging buffer.
    __syncthreads();
    float* stage = (float*)&As[0][0] + warp * 256;   // 8 warps x 256 floats = 8KB

    const int r  = lane >> 1;
    const int c0 = (lane & 1) * 8;
#pragma unroll
    for (int ct = 0; ct < 4; ct++) {
        wmma::store_matrix_sync(stage, acc[ct], 16, wmma::mem_row_major);
        __syncwarp();
        const float* sp = stage + r * 16 + c0;
        __half2 h[4];
#pragma unroll
        for (int j = 0; j < 4; j++)
            h[j] = __floats2half2_rn(sp[2 * j], sp[2 * j + 1]);
        const int gr = block_row + srow + r;
        if (gr < M)
            *(uint4*)(g_XFh + (size_t)gr * NFEAT + scol + ct * 16 + c0) = *(const uint4*)h;
        __syncwarp();
    }
}

// ---------------------------------------------------------------------------
// Kernel C: SpMM — warp per dst node (round-7 proven shape: regs 32, occ 82%).
// fp32 accumulation, vectorized idx/weight loads, unroll 8.
// ---------------------------------------------------------------------------
__device__ __forceinline__ void edge_acc(float4& acc, int s, float w, int lane) {
    const uint2 hv = *(const uint2*)(g_XFh + (size_t)s * NFEAT + lane * 4);
    const float2 f0 = __half22float2(*reinterpret_cast<const __half2*>(&hv.x));
    const float2 f1 = __half22float2(*reinterpret_cast<const __half2*>(&hv.y));
    acc.x += w * f0.x;
    acc.y += w * f0.y;
    acc.z += w * f1.x;
    acc.w += w * f1.y;
}

__global__ __launch_bounds__(256)
void spmm_kernel(const int* __restrict__ esrc,
                 const float* __restrict__ ew,
                 float* __restrict__ out,
                 int N) {
    const int warp = (blockIdx.x * blockDim.x + threadIdx.x) >> 5;
    const int lane = threadIdx.x & 31;
    if (warp >= N) return;

    const int start = g_rowptr[warp];
    const int end   = g_rowptr[warp + 1];

    float4 acc = make_float4(0.f, 0.f, 0.f, 0.f);

    int e = start;
    while (e < end && (e & 3)) {
        edge_acc(acc, __ldg(esrc + e), __ldg(ew + e), lane);
        e++;
    }
    for (; e + 8 <= end; e += 8) {
        const int4   sa = __ldg((const int4*)(esrc + e));
        const int4   sb = __ldg((const int4*)(esrc + e + 4));
        const float4 wa = __ldg((const float4*)(ew + e));
        const float4 wb = __ldg((const float4*)(ew + e + 4));
        edge_acc(acc, sa.x, wa.x, lane);
        edge_acc(acc, sa.y, wa.y, lane);
        edge_acc(acc, sa.z, wa.z, lane);
        edge_acc(acc, sa.w, wa.w, lane);
        edge_acc(acc, sb.x, wb.x, lane);
        edge_acc(acc, sb.y, wb.y, lane);
        edge_acc(acc, sb.z, wb.z, lane);
        edge_acc(acc, sb.w, wb.w, lane);
    }
    for (; e + 4 <= end; e += 4) {
        const int4   sa = __ldg((const int4*)(esrc + e));
        const float4 wa = __ldg((const float4*)(ew + e));
        edge_acc(acc, sa.x, wa.x, lane);
        edge_acc(acc, sa.y, wa.y, lane);
        edge_acc(acc, sa.z, wa.z, lane);
        edge_acc(acc, sa.w, wa.w, lane);
    }
    for (; e < end; e++)
        edge_acc(acc, __ldg(esrc + e), __ldg(ew + e), lane);

    *(float4*)(out + (size_t)warp * NFEAT + (size_t)lane * 4) = acc;
}

// ---------------------------------------------------------------------------
// Launch: rowptr -> gemm -> spmm (graph-capturable)
// ---------------------------------------------------------------------------
extern "C" void kernel_launch(void* const* d_in, const int* in_sizes, int n_in,
                              void* d_out, int out_size) {
    const float* x       = (const float*)d_in[0];
    const float* filters = (const float*)d_in[1];
    const int*   esrc    = (const int*)d_in[2];
    const int*   edst    = (const int*)d_in[3];
    const float* ew      = (const float*)d_in[4];
    float*       out     = (float*)d_out;

    const int M = in_sizes[0] / NFEAT;   // 100000 nodes
    const int E = in_sizes[4];           // 3200000 edges

    const int rthreads = (E + 3) / 4;
    rowptr_kernel<<<(rthreads + 255) / 256, 256>>>(edst, E, M);

    gemm_wmma_kernel<<<(M + GB_BM - 1) / GB_BM, 256>>>(x, filters, M);

    const long long nthreads = (long long)M * 32;
    spmm_kernel<<<(int)((nthreads + 255) / 256), 256>>>(esrc, ew, out, M);
}

// round 17
// speedup vs baseline: 1.1156x; 1.1156x over previous
#include <cuda_runtime.h>
#include <cuda_fp16.h>
#include <mma.h>
#include <cstdint>

using namespace nvcuda;

#define N_NODES_MAX 100000
#define NFEAT 128

// Scratch (allocation-free rule: __device__ globals, referenced only in kernels)
__device__ __half g_XFh[(size_t)N_NODES_MAX * NFEAT];   // XF in fp16
__device__ int    g_rowptr[N_NODES_MAX + 1];            // CSR row pointer

// ---------------------------------------------------------------------------
// Fused prep kernel: every block does (a) a 2048-edge rowptr slice, then
// (b) one 64x128 GEMM tile. The rowptr stores are fire-and-forget and hide
// inside the GEMM's load-phase latency. 2 kernels total for the whole op.
// ---------------------------------------------------------------------------
#define GB_BM 64
#define LDM 136          // 128 + 8 halves pad
#define EPB 2048         // edges per block for the rowptr slice (8/thread)

__global__ __launch_bounds__(256)
void prep_kernel(const float* __restrict__ A,        // x [M,128]
                 const float* __restrict__ F,        // filters [128,128] fp32
                 const int*   __restrict__ edst,     // sorted dst [E]
                 int M, int E) {
    __shared__ __half Bs[NFEAT][LDM];          // filters fp16, 34.8KB
    __shared__ __half As[GB_BM][LDM];          // x tile fp16, 17.4KB
    __shared__ float  stage[8][16 * 16];       // per-warp staging, 8KB

    const int tid  = threadIdx.x;
    const int warp = tid >> 5;
    const int lane = tid & 31;
    const int block_row = blockIdx.x * GB_BM;

    // ---------------- (a) rowptr slice: 8 edges/thread, two int4 loads -----
    {
        const int e0 = blockIdx.x * EPB + tid * 8;
        if (e0 < E) {
            int d[8];
            int nvalid;
            if (e0 + 8 <= E) {
                const int4 d4a = __ldg((const int4*)(edst + e0));
                const int4 d4b = __ldg((const int4*)(edst + e0 + 4));
                d[0] = d4a.x; d[1] = d4a.y; d[2] = d4a.z; d[3] = d4a.w;
                d[4] = d4b.x; d[5] = d4b.y; d[6] = d4b.z; d[7] = d4b.w;
                nvalid = 8;
            } else {
                nvalid = E - e0;
                for (int i = 0; i < nvalid; i++) d[i] = __ldg(edst + e0 + i);
            }
            int prev = (e0 == 0) ? -1 : __ldg(edst + e0 - 1);
#pragma unroll
            for (int i = 0; i < 8; i++) {
                if (i < nvalid) {
                    for (int dd = prev + 1; dd <= d[i]; dd++) g_rowptr[dd] = e0 + i;
                    prev = d[i];
                }
            }
            if (e0 + 8 >= E) {   // thread owning the final edge fills the tail
                for (int dd = prev + 1; dd <= M; dd++) g_rowptr[dd] = E;
            }
        }
    }

    // ---------------- (b) GEMM tile ----------------------------------------
    // Inline filter convert: 4096 float4 groups, 16 per thread (coalesced)
#pragma unroll
    for (int i = 0; i < 16; i++) {
        const int g   = tid + i * 256;
        const int row = g >> 5;
        const int col = (g & 31) << 2;
        const float4 v = *(const float4*)(F + (size_t)row * NFEAT + col);
        *(__half2*)&Bs[row][col + 0] = __floats2half2_rn(v.x, v.y);
        *(__half2*)&Bs[row][col + 2] = __floats2half2_rn(v.z, v.w);
    }

    // Load + convert x tile: 64x128 fp32 -> fp16 SMEM (8 float4 per thread)
#pragma unroll
    for (int i = 0; i < 8; i++) {
        const int idx = tid + i * 256;
        const int row = idx >> 5;
        const int col = (idx & 31) << 2;
        const int gr  = block_row + row;
        float4 v;
        if (gr < M)
            v = *(const float4*)(A + (size_t)gr * NFEAT + col);
        else
            v = make_float4(0.f, 0.f, 0.f, 0.f);
        *(__half2*)&As[row][col + 0] = __floats2half2_rn(v.x, v.y);
        *(__half2*)&As[row][col + 2] = __floats2half2_rn(v.z, v.w);
    }
    __syncthreads();

    // MMA: warp owns 16 rows x 64 cols
    const int srow = (warp >> 1) * 16;
    const int scol = (warp & 1) * 64;

    wmma::fragment<wmma::accumulator, 16, 16, 16, float> acc[4];
#pragma unroll
    for (int ct = 0; ct < 4; ct++) wmma::fill_fragment(acc[ct], 0.0f);

#pragma unroll
    for (int kt = 0; kt < 8; kt++) {
        wmma::fragment<wmma::matrix_a, 16, 16, 16, __half, wmma::row_major> a_frag;
        wmma::load_matrix_sync(a_frag, &As[srow][kt * 16], LDM);
#pragma unroll
        for (int ct = 0; ct < 4; ct++) {
            wmma::fragment<wmma::matrix_b, 16, 16, 16, __half, wmma::row_major> b_frag;
            wmma::load_matrix_sync(b_frag, &Bs[kt * 16][scol + ct * 16], LDM);
            wmma::mma_sync(acc[ct], a_frag, b_frag, acc[ct]);
        }
    }

    // Store: stage f32 per col-tile, convert to fp16, 16B/thread writes
    const int r  = lane >> 1;
    const int c0 = (lane & 1) * 8;
#pragma unroll
    for (int ct = 0; ct < 4; ct++) {
        wmma::store_matrix_sync(&stage[warp][0], acc[ct], 16, wmma::mem_row_major);
        __syncwarp();
        const float* sp = &stage[warp][r * 16 + c0];
        __half2 h[4];
#pragma unroll
        for (int j = 0; j < 4; j++)
            h[j] = __floats2half2_rn(sp[2 * j], sp[2 * j + 1]);
        const int gr = block_row + srow + r;
        if (gr < M)
            *(uint4*)(g_XFh + (size_t)gr * NFEAT + scol + ct * 16 + c0) = *(const uint4*)h;
        __syncwarp();
    }
}

// ---------------------------------------------------------------------------
// Kernel C: SpMM — warp per dst node (round-7 proven shape: regs 32, occ 82%).
// fp32 accumulation, vectorized idx/weight loads, unroll 8.
// ---------------------------------------------------------------------------
__device__ __forceinline__ void edge_acc(float4& acc, int s, float w, int lane) {
    const uint2 hv = *(const uint2*)(g_XFh + (size_t)s * NFEAT + lane * 4);
    const float2 f0 = __half22float2(*reinterpret_cast<const __half2*>(&hv.x));
    const float2 f1 = __half22float2(*reinterpret_cast<const __half2*>(&hv.y));
    acc.x += w * f0.x;
    acc.y += w * f0.y;
    acc.z += w * f1.x;
    acc.w += w * f1.y;
}

__global__ __launch_bounds__(256)
void spmm_kernel(const int* __restrict__ esrc,
                 const float* __restrict__ ew,
                 float* __restrict__ out,
                 int N) {
    const int warp = (blockIdx.x * blockDim.x + threadIdx.x) >> 5;
    const int lane = threadIdx.x & 31;
    if (warp >= N) return;

    const int start = g_rowptr[warp];
    const int end   = g_rowptr[warp + 1];

    float4 acc = make_float4(0.f, 0.f, 0.f, 0.f);

    int e = start;
    while (e < end && (e & 3)) {
        edge_acc(acc, __ldg(esrc + e), __ldg(ew + e), lane);
        e++;
    }
    for (; e + 8 <= end; e += 8) {
        const int4   sa = __ldg((const int4*)(esrc + e));
        const int4   sb = __ldg((const int4*)(esrc + e + 4));
        const float4 wa = __ldg((const float4*)(ew + e));
        const float4 wb = __ldg((const float4*)(ew + e + 4));
        edge_acc(acc, sa.x, wa.x, lane);
        edge_acc(acc, sa.y, wa.y, lane);
        edge_acc(acc, sa.z, wa.z, lane);
        edge_acc(acc, sa.w, wa.w, lane);
        edge_acc(acc, sb.x, wb.x, lane);
        edge_acc(acc, sb.y, wb.y, lane);
        edge_acc(acc, sb.z, wb.z, lane);
        edge_acc(acc, sb.w, wb.w, lane);
    }
    for (; e + 4 <= end; e += 4) {
        const int4   sa = __ldg((const int4*)(esrc + e));
        const float4 wa = __ldg((const float4*)(ew + e));
        edge_acc(acc, sa.x, wa.x, lane);
        edge_acc(acc, sa.y, wa.y, lane);
        edge_acc(acc, sa.z, wa.z, lane);
        edge_acc(acc, sa.w, wa.w, lane);
    }
    for (; e < end; e++)
        edge_acc(acc, __ldg(esrc + e), __ldg(ew + e), lane);

    *(float4*)(out + (size_t)warp * NFEAT + (size_t)lane * 4) = acc;
}

// ---------------------------------------------------------------------------
// Launch: fused prep (rowptr embedded in gemm blocks) -> spmm. 2 kernels.
// ---------------------------------------------------------------------------
extern "C" void kernel_launch(void* const* d_in, const int* in_sizes, int n_in,
                              void* d_out, int out_size) {
    const float* x       = (const float*)d_in[0];
    const float* filters = (const float*)d_in[1];
    const int*   esrc    = (const int*)d_in[2];
    const int*   edst    = (const int*)d_in[3];
    const float* ew      = (const float*)d_in[4];
    float*       out     = (float*)d_out;

    const int M = in_sizes[0] / NFEAT;   // 100000 nodes
    const int E = in_sizes[4];           // 3200000 edges

    const int gblocks = (M + GB_BM - 1) / GB_BM;       // 1563
    // Rowptr coverage check: gblocks * EPB = 1563 * 2048 = 3,201,024 >= E. OK.
    prep_kernel<<<gblocks, 256>>>(x, filters, edst, M, E);

    const long long nthreads = (long long)M * 32;
    spmm_kernel<<<(int)((nthreads + 255) / 256), 256>>>(esrc, ew, out, M);
}